// round 12
// baseline (speedup 1.0000x reference)
#include <cuda_runtime.h>

// Problem constants (from reference): B=32, T=168, M=1024, A=8, H=64, O=1
#define Mu   1024
#define Au   8
#define Hu   64

// Coefficient table (AoS): per map-unit m
//   [m*3+0] = (u0,u1,u2,u3) ; [m*3+1] = (u4,u5,u6,u7)
//   [m*3+2] = (c_mn, c_mx, c_const, 0)
// u[a] = sum_h assoc_w[m,a,h]*dense_w[m,h];  v = sum_h assoc_b[m,h]*dense_w[m,h]
// s = sum_h dense_w[m,h];  U = sum_a u[a]
// c_mn = s - U - v ; c_mx = v ; c_const = dense_b[m]
// out = dot(xt,u) + mn*c_mn + mx*c_mx + c_const   (LSTM state is dead code;
// the /(mx-mn) and *(mx-mn) cancel algebraically).
__device__ float4 g_coef[Mu * 3];

__device__ __forceinline__ float warp_sum(float v) {
    #pragma unroll
    for (int off = 16; off > 0; off >>= 1)
        v += __shfl_xor_sync(0xffffffffu, v, off);
    return v;
}

// One warp per map-unit m; 8 warps/block -> 128 blocks; full-ILP reductions.
// PDL trigger after the coefficient stores.
__global__ void __launch_bounds__(256)
precompute_kernel(const float* __restrict__ assoc_w,   // [M,A,H]
                  const float* __restrict__ assoc_b,   // [M,H]
                  const float* __restrict__ dense_w,   // [M,H]
                  const float* __restrict__ dense_b) { // [M]
    const int warp = threadIdx.x >> 5;
    const int lane = threadIdx.x & 31;
    const int m = blockIdx.x * 8 + warp;   // grid = 128

    const float2 d  = reinterpret_cast<const float2*>(dense_w + m * Hu)[lane];
    const float2 ab = reinterpret_cast<const float2*>(assoc_b + m * Hu)[lane];

    float vals[10];
    #pragma unroll
    for (int a = 0; a < Au; a++) {
        const float2 w = reinterpret_cast<const float2*>(
            assoc_w + ((size_t)m * Au + a) * Hu)[lane];
        vals[a] = w.x * d.x + w.y * d.y;
    }
    vals[8] = ab.x * d.x + ab.y * d.y;   // v partial
    vals[9] = d.x + d.y;                 // s partial

    #pragma unroll
    for (int i = 0; i < 10; i++)
        vals[i] = warp_sum(vals[i]);

    if (lane == 0) {
        float U = vals[0] + vals[1] + vals[2] + vals[3]
                + vals[4] + vals[5] + vals[6] + vals[7];
        g_coef[m * 3 + 0] = make_float4(vals[0], vals[1], vals[2], vals[3]);
        g_coef[m * 3 + 1] = make_float4(vals[4], vals[5], vals[6], vals[7]);
        g_coef[m * 3 + 2] = make_float4(vals[9] - U - vals[8], vals[8],
                                        dense_b[m], 0.0f);
    }

    cudaTriggerProgrammaticLaunchCompletion();
}

// ~ one occupancy wave: 148 SMs x 6 resident blocks (regs~30 @ 256 thr)
#define WAVE_BLOCKS 888
#define WAVE_ELEMS  (WAVE_BLOCKS * 256)
#define BLOCK_BYTES (256 * 8 * 4)   // 8 KB of x per block (256 thr x 32 B)

// Flat 1-elem/thread streaming kernel + software prefetcher (R8/R10/R11
// finding: staging x lines 1-2 waves ahead in L2 turns the real LDGs into
// L2 hits and is worth ~1.3us). This round the prefetcher moves OFF the
// warp-issue path: ONE cp.async.bulk.prefetch.L2 per block per distance
// (8 KB each, issued by thread 0) replaces ~128 scalar prefetch ops and all
// their predicate/address ALU — hot-path SASS identical to the plain R3 body.
// n = 5,505,024 is an exact multiple of 256 -> no bounds check on idx.
__global__ void __launch_bounds__(256)
fused_kernel(const float* __restrict__ x,   // [B,T,M,A] contiguous
             float* __restrict__ out,       // [B,T,M]
             int n) {                       // n = B*T*M
    const int idx = blockIdx.x * blockDim.x + threadIdx.x;
    const int m   = idx & (Mu - 1);         // M = 1024, fastest dim

    const float4* xp = reinterpret_cast<const float4*>(x) + (size_t)idx * 2;
    const float4 a = __ldcs(xp);            // issued before the dependency wait
    const float4 b = __ldcs(xp + 1);

    // Bulk L2 prefetch of the wave+1 and wave+2 regions for this block slot.
    if (threadIdx.x == 0 && blockIdx.x + 2 * WAVE_BLOCKS < gridDim.x) {
        const char* base = reinterpret_cast<const char*>(x)
                         + (size_t)blockIdx.x * BLOCK_BYTES;
        const char* p1 = base + (size_t)WAVE_BLOCKS * BLOCK_BYTES;
        const char* p2 = base + (size_t)2 * WAVE_BLOCKS * BLOCK_BYTES;
        asm volatile("cp.async.bulk.prefetch.L2.global [%0], %1;"
                     :: "l"(p1), "r"(BLOCK_BYTES));
        asm volatile("cp.async.bulk.prefetch.L2.global [%0], %1;"
                     :: "l"(p2), "r"(BLOCK_BYTES));
    }

    cudaGridDependencySynchronize();        // g_coef now valid

    const float4 u0 = g_coef[m * 3 + 0];
    const float4 u1 = g_coef[m * 3 + 1];
    const float4 c  = g_coef[m * 3 + 2];

    float mn = fminf(fminf(fminf(a.x, a.y), fminf(a.z, a.w)),
                     fminf(fminf(b.x, b.y), fminf(b.z, b.w)));
    float mx = fmaxf(fmaxf(fmaxf(a.x, a.y), fmaxf(a.z, a.w)),
                     fmaxf(fmaxf(b.x, b.y), fmaxf(b.z, b.w)));

    float dot = a.x * u0.x + a.y * u0.y + a.z * u0.z + a.w * u0.w
              + b.x * u1.x + b.y * u1.y + b.z * u1.z + b.w * u1.w;

    __stcs(out + idx, dot + mn * c.x + mx * c.y + c.z);
}

extern "C" void kernel_launch(void* const* d_in, const int* in_sizes, int n_in,
                              void* d_out, int out_size) {
    // metadata order: input, assoc_w, assoc_b, w_ih, w_hh, b_ih, b_hh, dense_w, dense_b
    const float* x        = (const float*)d_in[0];
    const float* assoc_w  = (const float*)d_in[1];
    const float* assoc_b  = (const float*)d_in[2];
    const float* dense_w  = (const float*)d_in[7];
    const float* dense_b  = (const float*)d_in[8];
    float* out            = (float*)d_out;

    precompute_kernel<<<Mu / 8, 256>>>(assoc_w, assoc_b, dense_w, dense_b);

    const int n = out_size;                 // B*T*M = 5,505,024 = 21504 * 256
    const int threads = 256;
    const int blocks = n / threads;         // 21504

    // PDL: fused may begin launching before precompute completes; the
    // device-side cudaGridDependencySynchronize() orders the coef reads.
    cudaLaunchConfig_t cfg = {};
    cfg.gridDim  = dim3(blocks, 1, 1);
    cfg.blockDim = dim3(threads, 1, 1);
    cfg.dynamicSmemBytes = 0;
    cfg.stream = 0;
    cudaLaunchAttribute attr[1];
    attr[0].id = cudaLaunchAttributeProgrammaticStreamSerialization;
    attr[0].val.programmaticStreamSerializationAllowed = 1;
    cfg.attrs = attr;
    cfg.numAttrs = 1;
    cudaLaunchKernelEx(&cfg, fused_kernel, x, out, n);
}

// round 13
// speedup vs baseline: 1.0910x; 1.0910x over previous
#include <cuda_runtime.h>

// Problem constants (from reference): B=32, T=168, M=1024, A=8, H=64, O=1
#define Mu   1024
#define Au   8
#define Hu   64

// Coefficient table (AoS): per map-unit m
//   [m*3+0] = (u0,u1,u2,u3) ; [m*3+1] = (u4,u5,u6,u7)
//   [m*3+2] = (c_mn, c_mx, c_const, 0)
// u[a] = sum_h assoc_w[m,a,h]*dense_w[m,h];  v = sum_h assoc_b[m,h]*dense_w[m,h]
// s = sum_h dense_w[m,h];  U = sum_a u[a]
// c_mn = s - U - v ; c_mx = v ; c_const = dense_b[m]
// out = dot(xt,u) + mn*c_mn + mx*c_mx + c_const   (LSTM state is dead code;
// the /(mx-mn) and *(mx-mn) cancel algebraically).
__device__ float4 g_coef[Mu * 3];

__device__ __forceinline__ float warp_sum(float v) {
    #pragma unroll
    for (int off = 16; off > 0; off >>= 1)
        v += __shfl_xor_sync(0xffffffffu, v, off);
    return v;
}

// One warp per map-unit m; 8 warps/block -> 128 blocks; full-ILP reductions.
// PDL trigger after the coefficient stores.
__global__ void __launch_bounds__(256)
precompute_kernel(const float* __restrict__ assoc_w,   // [M,A,H]
                  const float* __restrict__ assoc_b,   // [M,H]
                  const float* __restrict__ dense_w,   // [M,H]
                  const float* __restrict__ dense_b) { // [M]
    const int warp = threadIdx.x >> 5;
    const int lane = threadIdx.x & 31;
    const int m = blockIdx.x * 8 + warp;   // grid = 128

    const float2 d  = reinterpret_cast<const float2*>(dense_w + m * Hu)[lane];
    const float2 ab = reinterpret_cast<const float2*>(assoc_b + m * Hu)[lane];

    float vals[10];
    #pragma unroll
    for (int a = 0; a < Au; a++) {
        const float2 w = reinterpret_cast<const float2*>(
            assoc_w + ((size_t)m * Au + a) * Hu)[lane];
        vals[a] = w.x * d.x + w.y * d.y;
    }
    vals[8] = ab.x * d.x + ab.y * d.y;   // v partial
    vals[9] = d.x + d.y;                 // s partial

    #pragma unroll
    for (int i = 0; i < 10; i++)
        vals[i] = warp_sum(vals[i]);

    if (lane == 0) {
        float U = vals[0] + vals[1] + vals[2] + vals[3]
                + vals[4] + vals[5] + vals[6] + vals[7];
        g_coef[m * 3 + 0] = make_float4(vals[0], vals[1], vals[2], vals[3]);
        g_coef[m * 3 + 1] = make_float4(vals[4], vals[5], vals[6], vals[7]);
        g_coef[m * 3 + 2] = make_float4(vals[9] - U - vals[8], vals[8],
                                        dense_b[m], 0.0f);
    }

    cudaTriggerProgrammaticLaunchCompletion();
}

// ~ one occupancy wave: 148 SMs x 6 resident blocks (regs~30 @ 256 thr)
#define WAVE_BLOCKS 888
#define WAVE_ELEMS  (WAVE_BLOCKS * 256)

// Flat 1-elem/thread streaming kernel with a grid-wide software prefetcher
// (R8/R10/R11: staging x lines ahead in L2 turns real LDGs into L2 hits,
// worth ~1.3us; scalar prefetch beats cp.async.bulk — R12).
// Minimal redundancy: each 128B line is shared by 4 consecutive threads;
// exactly ONE of them ((idx&3)==0) prefetches the line 2 waves ahead.
// Single staging point suffices: 2 waves of x (~14MB) never evicts from the
// 126MB L2 before use. 0.25 prefetch ops/thread (was 0.5 in R11).
// n = 5,505,024 is an exact multiple of 256 -> no bounds check on idx.
__global__ void __launch_bounds__(256)
fused_kernel(const float* __restrict__ x,   // [B,T,M,A] contiguous
             float* __restrict__ out,       // [B,T,M]
             int n) {                       // n = B*T*M
    const int idx = blockIdx.x * blockDim.x + threadIdx.x;
    const int m   = idx & (Mu - 1);         // M = 1024, fastest dim

    const float4* xp = reinterpret_cast<const float4*>(x) + (size_t)idx * 2;
    const float4 a = __ldcs(xp);            // issued before the dependency wait
    const float4 b = __ldcs(xp + 1);

    // One prefetch per 128B line, 2 waves ahead (uniform range guard).
    if ((idx & 3) == 0 && blockIdx.x + 2 * WAVE_BLOCKS < gridDim.x) {
        const float4* p = reinterpret_cast<const float4*>(x)
                        + ((size_t)idx + 2 * WAVE_ELEMS) * 2;
        asm volatile("prefetch.global.L2 [%0];" :: "l"(p));
    }

    cudaGridDependencySynchronize();        // g_coef now valid

    const float4 u0 = g_coef[m * 3 + 0];
    const float4 u1 = g_coef[m * 3 + 1];
    const float4 c  = g_coef[m * 3 + 2];

    float mn = fminf(fminf(fminf(a.x, a.y), fminf(a.z, a.w)),
                     fminf(fminf(b.x, b.y), fminf(b.z, b.w)));
    float mx = fmaxf(fmaxf(fmaxf(a.x, a.y), fmaxf(a.z, a.w)),
                     fmaxf(fmaxf(b.x, b.y), fmaxf(b.z, b.w)));

    float dot = a.x * u0.x + a.y * u0.y + a.z * u0.z + a.w * u0.w
              + b.x * u1.x + b.y * u1.y + b.z * u1.z + b.w * u1.w;

    __stcs(out + idx, dot + mn * c.x + mx * c.y + c.z);
}

extern "C" void kernel_launch(void* const* d_in, const int* in_sizes, int n_in,
                              void* d_out, int out_size) {
    // metadata order: input, assoc_w, assoc_b, w_ih, w_hh, b_ih, b_hh, dense_w, dense_b
    const float* x        = (const float*)d_in[0];
    const float* assoc_w  = (const float*)d_in[1];
    const float* assoc_b  = (const float*)d_in[2];
    const float* dense_w  = (const float*)d_in[7];
    const float* dense_b  = (const float*)d_in[8];
    float* out            = (float*)d_out;

    precompute_kernel<<<Mu / 8, 256>>>(assoc_w, assoc_b, dense_w, dense_b);

    const int n = out_size;                 // B*T*M = 5,505,024 = 21504 * 256
    const int threads = 256;
    const int blocks = n / threads;         // 21504

    // PDL: fused may begin launching before precompute completes; the
    // device-side cudaGridDependencySynchronize() orders the coef reads.
    cudaLaunchConfig_t cfg = {};
    cfg.gridDim  = dim3(blocks, 1, 1);
    cfg.blockDim = dim3(threads, 1, 1);
    cfg.dynamicSmemBytes = 0;
    cfg.stream = 0;
    cudaLaunchAttribute attr[1];
    attr[0].id = cudaLaunchAttributeProgrammaticStreamSerialization;
    attr[0].val.programmaticStreamSerializationAllowed = 1;
    cfg.attrs = attr;
    cfg.numAttrs = 1;
    cudaLaunchKernelEx(&cfg, fused_kernel, x, out, n);
}